// round 16
// baseline (speedup 1.0000x reference)
#include <cuda_runtime.h>
#include <cuda_fp16.h>

#define T_STEPS  2048
#define BATCH    4096
#define INSZ     8
#define HID      20
#define G4       80
#define GROUPS   3       // batch elems per CTA (1 per thread group)
#define NTHREADS 64      // 2 warps; 60 active lanes
#define ROWH     24      // padded smem row (half2): (h,h)[0:20], pad (96 B)

// hardware tanh: 1 MUFU op
__device__ __forceinline__ float tanh_hw(float v) {
    float r;
    asm("tanh.approx.f32 %0, %1;" : "=f"(r) : "f"(v));
    return r;
}
__device__ __forceinline__ float sigmoid_hw(float v) {
    return fmaf(tanh_hw(0.5f * v), 0.5f, 0.5f);
}

__global__ void __launch_bounds__(NTHREADS)
lstm_kernel(const float* __restrict__ x,    // [T, B, 8]
            const float* __restrict__ Wih,  // [8, 80]
            const float* __restrict__ bih,  // [80]
            const float* __restrict__ Whh,  // [20, 80]
            const float* __restrict__ bhh,  // [80]
            const float* __restrict__ hx0,  // [1, 20]
            const float* __restrict__ cx0,  // [1, 20]
            float* __restrict__ out)        // [B, 20]
{
    // each entry: half2 = (h, h) duplicated, ready for gate-pair HFMA2
    __shared__ __align__(16) __half2 sv[2][GROUPS][ROWH];

    const int tid = threadIdx.x;
    const bool active = (tid < GROUPS * HID);   // 60 of 64
    const int tc  = active ? tid : 0;
    const int g   = tc / HID;             // 0..2
    const int j   = tc % HID;             // 0..19
    const int b   = blockIdx.x * GROUPS + g;
    const bool ok = active && (b < BATCH);
    const int cb  = (b < BATCH) ? b : 0;

    // ---- recurrent weights, gate-pair packed half2 (40 regs) ----
    // wh2[k][0] = (Whh[k][i_col], Whh[k][f_col]); wh2[k][1] = (g_col, o_col)
    __half2 wh2[HID][2];
#pragma unroll
    for (int k = 0; k < HID; k++) {
        wh2[k][0] = __floats2half2_rn(__ldg(&Whh[k * G4 + 0 * HID + j]),
                                      __ldg(&Whh[k * G4 + 1 * HID + j]));
        wh2[k][1] = __floats2half2_rn(__ldg(&Whh[k * G4 + 2 * HID + j]),
                                      __ldg(&Whh[k * G4 + 3 * HID + j]));
    }

    // ---- input weights fp32 (32 regs) ----
    float wx[INSZ][4];
#pragma unroll
    for (int k = 0; k < INSZ; k++)
#pragma unroll
        for (int q = 0; q < 4; q++)
            wx[k][q] = __ldg(&Wih[k * G4 + q * HID + j]);

    float bias[4];
#pragma unroll
    for (int q = 0; q < 4; q++)
        bias[q] = __ldg(&bih[q * HID + j]) + __ldg(&bhh[q * HID + j]);

    float h = hx0[j], c = cx0[j];

    const float4* x4 = reinterpret_cast<const float4*>(x);
    // float4 index for (t, b, half): (t*BATCH + b)*2 + half

    // ---- prologue: xacc = bias + x_0 * W_ih (fp32, exact) ----
    float xacc[4];
    {
        const float4 a0 = x4[(0 * BATCH + cb) * 2 + 0];
        const float4 a1 = x4[(0 * BATCH + cb) * 2 + 1];
        const float xs[8] = {a0.x, a0.y, a0.z, a0.w, a1.x, a1.y, a1.z, a1.w};
#pragma unroll
        for (int q = 0; q < 4; q++) xacc[q] = bias[q];
#pragma unroll
        for (int k = 0; k < INSZ; k++)
#pragma unroll
            for (int q = 0; q < 4; q++)
                xacc[q] = fmaf(xs[k], wx[k][q], xacc[q]);
    }

    if (active)
        sv[0][g][j] = __half2half2(__float2half_rn(h));
    __syncthreads();

    int cur = 0;
#pragma unroll 2
    for (int t = 0; t < T_STEPS; t++) {
        const int nxt = cur ^ 1;

        // ---- x loads for step t+1 (latency hidden by HFMA2 block) ----
        const int tn = (t + 1 < T_STEPS) ? (t + 1) : t;
        const float4 xa = x4[((size_t)tn * BATCH + cb) * 2 + 0];
        const float4 xb = x4[((size_t)tn * BATCH + cb) * 2 + 1];

        // ---- gate-pair packed accumulation: (i,f) and (g,o), 2 k-partials each ----
        __half2 acc[2][2];
        acc[0][0] = __float2half2_rn(0.0f);
        acc[0][1] = __float2half2_rn(0.0f);
        acc[1][0] = __float2half2_rn(0.0f);
        acc[1][1] = __float2half2_rn(0.0f);

        const float4* r = reinterpret_cast<const float4*>(sv[cur][g]);  // 5 x float4 = 20 half2
#pragma unroll
        for (int kc = 0; kc < HID / 4; kc++) {
            const float4 blk = r[kc];
            __half2 hp[4];
            hp[0] = *reinterpret_cast<const __half2*>(&blk.x);
            hp[1] = *reinterpret_cast<const __half2*>(&blk.y);
            hp[2] = *reinterpret_cast<const __half2*>(&blk.z);
            hp[3] = *reinterpret_cast<const __half2*>(&blk.w);
            const int k = kc * 4;
#pragma unroll
            for (int s = 0; s < 4; s++) {
                acc[0][s & 1] = __hfma2(hp[s], wh2[k + s][0], acc[0][s & 1]);
                acc[1][s & 1] = __hfma2(hp[s], wh2[k + s][1], acc[1][s & 1]);
            }
        }

        // ---- combine partials, unpack, add fp32 x-part ----
        const float2 fif = __half22float2(__hadd2(acc[0][0], acc[0][1]));
        const float2 fgo = __half22float2(__hadd2(acc[1][0], acc[1][1]));
        const float ai = xacc[0] + fif.x;
        const float af = xacc[1] + fif.y;
        const float ag = xacc[2] + fgo.x;
        const float ao = xacc[3] + fgo.y;

        // ---- activations (1 MUFU each) ----
        const float ii = sigmoid_hw(ai);
        const float ff = sigmoid_hw(af);
        const float gg = tanh_hw(ag);
        const float oo = sigmoid_hw(ao);

        // ---- next step's x-projection (fp32, fills MUFU shadow) ----
        {
            const float xs[8] = {xa.x, xa.y, xa.z, xa.w, xb.x, xb.y, xb.z, xb.w};
#pragma unroll
            for (int q = 0; q < 4; q++) xacc[q] = bias[q];
#pragma unroll
            for (int k = 0; k < INSZ; k++)
#pragma unroll
                for (int q = 0; q < 4; q++)
                    xacc[q] = fmaf(xs[k], wx[k][q], xacc[q]);
        }

        // ---- state update (fp32 c) ----
        c = ff * c + ii * gg;
        h = oo * tanh_hw(c);

        if (t + 1 < T_STEPS) {
            if (active)
                sv[nxt][g][j] = __half2half2(__float2half_rn(h));
            __syncthreads();
        }
        cur = nxt;
    }

    if (ok) out[b * HID + j] = h;
}

extern "C" void kernel_launch(void* const* d_in, const int* in_sizes, int n_in,
                              void* d_out, int out_size) {
    const float* x   = (const float*)d_in[0];
    const float* Wih = (const float*)d_in[1];
    const float* bih = (const float*)d_in[2];
    const float* Whh = (const float*)d_in[3];
    const float* bhh = (const float*)d_in[4];
    const float* hx0 = (const float*)d_in[5];
    const float* cx0 = (const float*)d_in[6];
    float* out = (float*)d_out;

    const int grid = (BATCH + GROUPS - 1) / GROUPS;  // 1366
    lstm_kernel<<<grid, NTHREADS>>>(x, Wih, bih, Whh, bhh, hx0, cx0, out);
}